// round 5
// baseline (speedup 1.0000x reference)
#include <cuda_runtime.h>
#include <cuda_bf16.h>
#include <cstdint>
#include <math.h>

#define NN 16384
#define DD 32
#define TILE 128
#define SPAD 40  // padded k-stride (bf16 elems): 80B rows -> 16B aligned, ldmatrix conflict-free

// Scratch (device globals: allocation-free per harness rules)
__device__ __align__(16) __nv_bfloat16 g_mub[NN * DD];
__device__ float g_sq[NN];
__device__ float g_foc[NN];

// ---------------------------------------------------------------------------
// Kernel 0: per-row precompute — sq[i] = ||mu_i||^2, bf16 copy of mus,
// foc[i] = exp(tanh(mu_i @ W1 + b1) @ W2 + b2)   (all fp32-exact)
// ---------------------------------------------------------------------------
__global__ void prep_kernel(const float* __restrict__ mus,
                            const float* __restrict__ W1,
                            const float* __restrict__ b1,
                            const float* __restrict__ W2,
                            const float* __restrict__ b2) {
    __shared__ float W1s[DD * DD];
    __shared__ float b1s[DD];
    __shared__ float W2s[DD];
    int t = threadIdx.x;
    for (int i = t; i < DD * DD; i += blockDim.x) W1s[i] = W1[i];
    if (t < DD) { b1s[t] = b1[t]; W2s[t] = W2[t]; }
    __syncthreads();

    int row = blockIdx.x * blockDim.x + t;
    if (row >= NN) return;

    float x[DD];
    float sq = 0.f;
#pragma unroll
    for (int k = 0; k < DD; k++) {
        x[k] = mus[row * DD + k];
        sq = fmaf(x[k], x[k], sq);
    }
    g_sq[row] = sq;
#pragma unroll
    for (int k = 0; k < DD; k++) g_mub[row * DD + k] = __float2bfloat16(x[k]);

    float acc2 = b2[0];
#pragma unroll
    for (int j = 0; j < DD; j++) {
        float a = b1s[j];
#pragma unroll
        for (int k = 0; k < DD; k++) a = fmaf(x[k], W1s[k * DD + j], a);
        acc2 = fmaf(tanhf(a), W2s[j], acc2);
    }
    g_foc[row] = expf(acc2);
}

// ---------------------------------------------------------------------------
// Kernel 1: 128x128 output tile per block (256 threads / 8 warps, warp grid 2x4,
// each warp computes 64x32). bf16 HMMA m16n8k16, fused exp epilogue + diag add.
// Epilogue uses exp2: K0 * exp(NEGC*e) == exp2f(LOG2K0 + NEGC_L2*e)
// -> one FMA + one EX2 per element (no separate multiply).
// ---------------------------------------------------------------------------
__global__ __launch_bounds__(256) void lens_kernel(float* __restrict__ out,
                                                   float LOG2K0, float NEGC_L2) {
    __shared__ __align__(16) __nv_bfloat16 As[TILE * SPAD];
    __shared__ __align__(16) __nv_bfloat16 Bs[TILE * SPAD];
    __shared__ float sqa[TILE];
    __shared__ float sqb[TILE];

    const int bi = blockIdx.y * TILE;  // global row base
    const int bj = blockIdx.x * TILE;  // global col base
    const int t = threadIdx.x;

    // Cooperative tile load: 128 rows x 32 bf16 (64B/row). Each thread moves 32B.
    {
        int row = t >> 1, part = t & 1;
        const uint4* srcA = reinterpret_cast<const uint4*>(g_mub + (size_t)(bi + row) * DD) + part * 2;
        uint4* dstA = reinterpret_cast<uint4*>(As + row * SPAD + part * 16);
        dstA[0] = srcA[0];
        dstA[1] = srcA[1];
        const uint4* srcB = reinterpret_cast<const uint4*>(g_mub + (size_t)(bj + row) * DD) + part * 2;
        uint4* dstB = reinterpret_cast<uint4*>(Bs + row * SPAD + part * 16);
        dstB[0] = srcB[0];
        dstB[1] = srcB[1];
        if (t < TILE) sqa[t] = g_sq[bi + t];
        else          sqb[t - TILE] = g_sq[bj + (t - TILE)];
    }
    __syncthreads();

    const int w = t >> 5, lane = t & 31;
    const int wm = (w >> 2) * 64;  // warp row offset in tile
    const int wn = (w & 3) * 32;   // warp col offset in tile

    // B fragments: 4 n-tiles x 2 k-steps x 2 regs. ldmatrix.x2 (non-trans):
    // lanes 0-7 -> rows n..n+7 @ kbase, lanes 8-15 -> rows @ kbase+8.
    uint32_t bfr[4][2][2];
    {
        const int l = lane & 15;
#pragma unroll
        for (int ni = 0; ni < 4; ni++) {
#pragma unroll
            for (int ks = 0; ks < 2; ks++) {
                const __nv_bfloat16* p =
                    Bs + (wn + ni * 8 + (l & 7)) * SPAD + ks * 16 + (l >> 3) * 8;
                uint32_t addr = (uint32_t)__cvta_generic_to_shared(p);
                asm volatile(
                    "ldmatrix.sync.aligned.m8n8.x2.shared.b16 {%0,%1}, [%2];"
                    : "=r"(bfr[ni][ks][0]), "=r"(bfr[ni][ks][1])
                    : "r"(addr));
            }
        }
    }

#pragma unroll
    for (int mi = 0; mi < 4; mi++) {
        // A fragments for this 16-row strip: 2 k-steps x 4 regs
        uint32_t afr[2][4];
#pragma unroll
        for (int ks = 0; ks < 2; ks++) {
            const __nv_bfloat16* p =
                As + (wm + mi * 16 + (lane & 15)) * SPAD + ks * 16 + (lane >> 4) * 8;
            uint32_t addr = (uint32_t)__cvta_generic_to_shared(p);
            asm volatile(
                "ldmatrix.sync.aligned.m8n8.x4.shared.b16 {%0,%1,%2,%3}, [%4];"
                : "=r"(afr[ks][0]), "=r"(afr[ks][1]), "=r"(afr[ks][2]), "=r"(afr[ks][3])
                : "r"(addr));
        }

        const int r0l = wm + mi * 16 + (lane >> 2);  // local row (acc rows g, g+8)
        const int r1l = r0l + 8;
        const float sqi0 = sqa[r0l];
        const float sqi1 = sqa[r1l];
        const int gr0 = bi + r0l;
        const int gr1 = bi + r1l;

#pragma unroll
        for (int ni = 0; ni < 4; ni++) {
            float c0 = 0.f, c1 = 0.f, c2 = 0.f, c3 = 0.f;
#pragma unroll
            for (int ks = 0; ks < 2; ks++) {
                asm volatile(
                    "mma.sync.aligned.m16n8k16.row.col.f32.bf16.bf16.f32 "
                    "{%0,%1,%2,%3}, {%4,%5,%6,%7}, {%8,%9}, {%0,%1,%2,%3};"
                    : "+f"(c0), "+f"(c1), "+f"(c2), "+f"(c3)
                    : "r"(afr[ks][0]), "r"(afr[ks][1]), "r"(afr[ks][2]), "r"(afr[ks][3]),
                      "r"(bfr[ni][ks][0]), "r"(bfr[ni][ks][1]));
            }

            const int cl = wn + ni * 8 + 2 * (lane & 3);  // local col of c0/c2
            const float sqj0 = sqb[cl];
            const float sqj1 = sqb[cl + 1];
            const int gc = bj + cl;

            float e0 = fmaxf(fmaf(-2.f, c0, sqi0 + sqj0), 0.f);
            float e1 = fmaxf(fmaf(-2.f, c1, sqi0 + sqj1), 0.f);
            float e2 = fmaxf(fmaf(-2.f, c2, sqi1 + sqj0), 0.f);
            float e3 = fmaxf(fmaf(-2.f, c3, sqi1 + sqj1), 0.f);

            float v0 = exp2f(fmaf(NEGC_L2, e0, LOG2K0));
            float v1 = exp2f(fmaf(NEGC_L2, e1, LOG2K0));
            float v2 = exp2f(fmaf(NEGC_L2, e2, LOG2K0));
            float v3 = exp2f(fmaf(NEGC_L2, e3, LOG2K0));

            // diagonal focalization (rare: only on diagonal blocks)
            if (gr0 == gc)     v0 += g_foc[gr0];
            if (gr0 == gc + 1) v1 += g_foc[gr0];
            if (gr1 == gc)     v2 += g_foc[gr1];
            if (gr1 == gc + 1) v3 += g_foc[gr1];

            // Streaming stores: output is write-once/read-never — keep it from
            // evicting the L2-resident g_mub/g_sq working set.
            __stcs(reinterpret_cast<float2*>(out + (size_t)gr0 * NN + gc), make_float2(v0, v1));
            __stcs(reinterpret_cast<float2*>(out + (size_t)gr1 * NN + gc), make_float2(v2, v3));
        }
    }
}

// ---------------------------------------------------------------------------
extern "C" void kernel_launch(void* const* d_in, const int* in_sizes, int n_in,
                              void* d_out, int out_size) {
    const float* mus = (const float*)d_in[0];
    const float* W1  = (const float*)d_in[1];
    const float* b1  = (const float*)d_in[2];
    const float* W2  = (const float*)d_in[3];
    const float* b2  = (const float*)d_in[4];
    float* out = (float*)d_out;

    // K0 = (2*rho)^(d/2) * (2*pi*sigma2)^((1-2*rho)*d/2), rho=0.01, d=32, sigma2=1
    const double rho = 0.01;
    const double k0 = pow(2.0 * rho, DD / 2.0) *
                      pow(2.0 * 3.14159265358979323846, (1.0 - 2.0 * rho) * DD / 2.0);
    const float log2k0 = (float)(log2(k0));
    // exp(-rho/4 * e) == 2^(e * (-rho/4)*log2(e))
    const float negc_l2 = (float)(-(rho / 4.0) * 1.4426950408889634);

    prep_kernel<<<NN / 128, 128>>>(mus, W1, b1, W2, b2);

    dim3 grid(NN / TILE, NN / TILE);
    lens_kernel<<<grid, 256>>>(out, log2k0, negc_l2);
}